// round 6
// baseline (speedup 1.0000x reference)
#include <cuda_runtime.h>
#include <math.h>

// ---------------------------------------------------------------------------
// Problem constants (match reference)
// ---------------------------------------------------------------------------
#define BATCH 32
#define HSP 28
#define WSP 28
#define CH 384
#define TQN 785          // 1 + 28*28
#define TKN 197          // 1 + 14*14
#define NHEADS 6
#define HDIM 64
#define OHS 14
#define OWS 14
#define BN_EPS_F 1e-5f
#define SCALE_F 0.05103103630798287f   // 384^-0.5 (reference scales by DIM)

#define MQ (BATCH * TQN)   // 25120
#define MKV (BATCH * TKN)  // 6304

// ---------------------------------------------------------------------------
// Scratch (no cudaMalloc allowed -> __device__ globals)
// ---------------------------------------------------------------------------
__device__ float g_qin[BATCH * TQN * CH];
__device__ float g_kin[BATCH * TKN * CH];
__device__ float g_vin[BATCH * TKN * CH];
__device__ float g_q  [BATCH * TQN * CH];
__device__ float g_k  [BATCH * TKN * CH];
__device__ float g_v  [BATCH * TKN * CH];
__device__ float g_att[BATCH * TQN * CH];

// ---------------------------------------------------------------------------
// Depthwise 3x3 conv + BN, stride 1 (query path), float4 over channels.
// One thread = one (b, t, 4-channel group).
// ---------------------------------------------------------------------------
#define C4 (CH / 4)   // 96

__global__ __launch_bounds__(256) void convq_kernel(
    const float* __restrict__ x, const float* __restrict__ cw,
    const float* __restrict__ gam, const float* __restrict__ bet,
    const float* __restrict__ mu, const float* __restrict__ va)
{
    int idx = blockIdx.x * 256 + threadIdx.x;
    if (idx >= BATCH * TQN * C4) return;
    int c4 = idx % C4;
    int t = (idx / C4) % TQN;
    int b = idx / (C4 * TQN);
    int c = c4 * 4;
    float4* dst = (float4*)&g_qin[(b * TQN + t) * CH + c];
    if (t == 0) {
        *dst = *(const float4*)&x[(b * TQN) * CH + c];
        return;
    }
    int p = t - 1;
    int oy = p / WSP, ox = p - oy * WSP;

    float4 gm = *(const float4*)&gam[c];
    float4 vr = *(const float4*)&va[c];
    float4 bt = *(const float4*)&bet[c];
    float4 mn = *(const float4*)&mu[c];
    float inv0 = gm.x * rsqrtf(vr.x + BN_EPS_F);
    float inv1 = gm.y * rsqrtf(vr.y + BN_EPS_F);
    float inv2 = gm.z * rsqrtf(vr.z + BN_EPS_F);
    float inv3 = gm.w * rsqrtf(vr.w + BN_EPS_F);

    float a0 = 0.f, a1 = 0.f, a2 = 0.f, a3 = 0.f;
    #pragma unroll
    for (int ky = 0; ky < 3; ky++) {
        int iy = oy + ky - 1;
        if ((unsigned)iy >= HSP) continue;
        #pragma unroll
        for (int kx = 0; kx < 3; kx++) {
            int ix = ox + kx - 1;
            if ((unsigned)ix >= WSP) continue;
            float4 xv = *(const float4*)&x[(b * TQN + 1 + iy * WSP + ix) * CH + c];
            int ko = ky * 3 + kx;
            a0 += xv.x * cw[(c + 0) * 9 + ko];
            a1 += xv.y * cw[(c + 1) * 9 + ko];
            a2 += xv.z * cw[(c + 2) * 9 + ko];
            a3 += xv.w * cw[(c + 3) * 9 + ko];
        }
    }
    float4 o;
    o.x = a0 * inv0 + (bt.x - mn.x * inv0);
    o.y = a1 * inv1 + (bt.y - mn.y * inv1);
    o.z = a2 * inv2 + (bt.z - mn.z * inv2);
    o.w = a3 * inv3 + (bt.w - mn.w * inv3);
    *dst = o;
}

// ---------------------------------------------------------------------------
// Depthwise 3x3 conv + BN, stride 2, k and v fused, float4 over channels.
// ---------------------------------------------------------------------------
__global__ __launch_bounds__(256) void convkv_kernel(
    const float* __restrict__ x, const float* __restrict__ cw,
    const float* __restrict__ gam, const float* __restrict__ bet,
    const float* __restrict__ mu, const float* __restrict__ va)
{
    int idx = blockIdx.x * 256 + threadIdx.x;
    if (idx >= BATCH * TKN * C4) return;
    int c4 = idx % C4;
    int t = (idx / C4) % TKN;
    int b = idx / (C4 * TKN);
    int c = c4 * 4;
    float4* dk = (float4*)&g_kin[(b * TKN + t) * CH + c];
    float4* dv = (float4*)&g_vin[(b * TKN + t) * CH + c];
    if (t == 0) {
        float4 cls = *(const float4*)&x[(b * TQN) * CH + c];
        *dk = cls;
        *dv = cls;
        return;
    }
    int p = t - 1;
    int oy = p / OWS, ox = p - oy * OWS;

    int ck = CH + c, cv = 2 * CH + c;
    float4 gmk = *(const float4*)&gam[ck];
    float4 vrk = *(const float4*)&va[ck];
    float4 btk = *(const float4*)&bet[ck];
    float4 mnk = *(const float4*)&mu[ck];
    float4 gmv = *(const float4*)&gam[cv];
    float4 vrv = *(const float4*)&va[cv];
    float4 btv = *(const float4*)&bet[cv];
    float4 mnv = *(const float4*)&mu[cv];
    float ik0 = gmk.x * rsqrtf(vrk.x + BN_EPS_F);
    float ik1 = gmk.y * rsqrtf(vrk.y + BN_EPS_F);
    float ik2 = gmk.z * rsqrtf(vrk.z + BN_EPS_F);
    float ik3 = gmk.w * rsqrtf(vrk.w + BN_EPS_F);
    float iv0 = gmv.x * rsqrtf(vrv.x + BN_EPS_F);
    float iv1 = gmv.y * rsqrtf(vrv.y + BN_EPS_F);
    float iv2 = gmv.z * rsqrtf(vrv.z + BN_EPS_F);
    float iv3 = gmv.w * rsqrtf(vrv.w + BN_EPS_F);

    float k0 = 0.f, k1 = 0.f, k2 = 0.f, k3 = 0.f;
    float v0 = 0.f, v1 = 0.f, v2 = 0.f, v3 = 0.f;
    #pragma unroll
    for (int ky = 0; ky < 3; ky++) {
        int iy = 2 * oy + ky - 1;
        if ((unsigned)iy >= HSP) continue;
        #pragma unroll
        for (int kx = 0; kx < 3; kx++) {
            int ix = 2 * ox + kx - 1;
            if ((unsigned)ix >= WSP) continue;
            float4 xv = *(const float4*)&x[(b * TQN + 1 + iy * WSP + ix) * CH + c];
            int ko = ky * 3 + kx;
            k0 += xv.x * cw[(ck + 0) * 9 + ko];
            k1 += xv.y * cw[(ck + 1) * 9 + ko];
            k2 += xv.z * cw[(ck + 2) * 9 + ko];
            k3 += xv.w * cw[(ck + 3) * 9 + ko];
            v0 += xv.x * cw[(cv + 0) * 9 + ko];
            v1 += xv.y * cw[(cv + 1) * 9 + ko];
            v2 += xv.z * cw[(cv + 2) * 9 + ko];
            v3 += xv.w * cw[(cv + 3) * 9 + ko];
        }
    }
    float4 ok, ov;
    ok.x = k0 * ik0 + (btk.x - mnk.x * ik0);
    ok.y = k1 * ik1 + (btk.y - mnk.y * ik1);
    ok.z = k2 * ik2 + (btk.z - mnk.z * ik2);
    ok.w = k3 * ik3 + (btk.w - mnk.w * ik3);
    ov.x = v0 * iv0 + (btv.x - mnv.x * iv0);
    ov.y = v1 * iv1 + (btv.y - mnv.y * iv1);
    ov.z = v2 * iv2 + (btv.z - mnv.z * iv2);
    ov.w = v3 * iv3 + (btv.w - mnv.w * iv3);
    *dk = ok;
    *dv = ov;
}

// ---------------------------------------------------------------------------
// fp32 GEMM body: C[M,384] = A[M,384] * W[384,384]^T (+ bias).
// 128x128 tile, BK=16, 256 threads, 8x8 reg tile, register-prefetch
// double-buffered SMEM with ONE __syncthreads per k-step (WAR/RAW proven).
// Inner loop: 4 LDS.128 + 64 FFMA per k-step, phase-conflict-free.
// ---------------------------------------------------------------------------
#define GBM 128
#define GBN 128
#define GBK 16
#define GSTR 132          // SMEM row stride (floats), multiple of 4
#define KSTEPS (CH / GBK) // 24

struct GemmSmem {
    float As[2][GBK][GSTR];
    float Bs[2][GBK][GSTR];
};

__device__ __forceinline__ void gemm_body(
    const float* __restrict__ A, const float* __restrict__ W,
    const float* __restrict__ bias, float* __restrict__ Cmat,
    int M, int m0, int n0, GemmSmem& sm)
{
    int tid = threadIdx.x;
    int tx = tid % 16;
    int ty = tid / 16;

    int rowA0 = tid >> 2,         kq = tid & 3;
    int rowA1 = (tid + 256) >> 2;                 // (tid+256)&3 == kq

    float4 pa0, pa1, pb0, pb1;

    auto load_regs = [&](int k0) {
        int m_0 = m0 + rowA0;
        int m_1 = m0 + rowA1;
        pa0 = (m_0 < M) ? *(const float4*)&A[(size_t)m_0 * CH + k0 + kq * 4]
                        : make_float4(0.f, 0.f, 0.f, 0.f);
        pa1 = (m_1 < M) ? *(const float4*)&A[(size_t)m_1 * CH + k0 + kq * 4]
                        : make_float4(0.f, 0.f, 0.f, 0.f);
        pb0 = *(const float4*)&W[(size_t)(n0 + rowA0) * CH + k0 + kq * 4];
        pb1 = *(const float4*)&W[(size_t)(n0 + rowA1) * CH + k0 + kq * 4];
    };
    auto store_smem = [&](int buf) {
        sm.As[buf][kq * 4 + 0][rowA0] = pa0.x;
        sm.As[buf][kq * 4 + 1][rowA0] = pa0.y;
        sm.As[buf][kq * 4 + 2][rowA0] = pa0.z;
        sm.As[buf][kq * 4 + 3][rowA0] = pa0.w;
        sm.As[buf][kq * 4 + 0][rowA1] = pa1.x;
        sm.As[buf][kq * 4 + 1][rowA1] = pa1.y;
        sm.As[buf][kq * 4 + 2][rowA1] = pa1.z;
        sm.As[buf][kq * 4 + 3][rowA1] = pa1.w;
        sm.Bs[buf][kq * 4 + 0][rowA0] = pb0.x;
        sm.Bs[buf][kq * 4 + 1][rowA0] = pb0.y;
        sm.Bs[buf][kq * 4 + 2][rowA0] = pb0.z;
        sm.Bs[buf][kq * 4 + 3][rowA0] = pb0.w;
        sm.Bs[buf][kq * 4 + 0][rowA1] = pb1.x;
        sm.Bs[buf][kq * 4 + 1][rowA1] = pb1.y;
        sm.Bs[buf][kq * 4 + 2][rowA1] = pb1.z;
        sm.Bs[buf][kq * 4 + 3][rowA1] = pb1.w;
    };

    float acc[8][8];
    #pragma unroll
    for (int i = 0; i < 8; i++)
        #pragma unroll
        for (int j = 0; j < 8; j++) acc[i][j] = 0.f;

    load_regs(0);
    store_smem(0);
    __syncthreads();

    #pragma unroll
    for (int it = 0; it < KSTEPS; it++) {
        int cur = it & 1;
        if (it + 1 < KSTEPS) load_regs((it + 1) * GBK);
        #pragma unroll
        for (int kk = 0; kk < GBK; kk++) {
            float4 a0 = *(const float4*)&sm.As[cur][kk][ty * 4];
            float4 a1 = *(const float4*)&sm.As[cur][kk][64 + ty * 4];
            float4 b0 = *(const float4*)&sm.Bs[cur][kk][tx * 4];
            float4 b1 = *(const float4*)&sm.Bs[cur][kk][64 + tx * 4];
            float ra[8] = {a0.x, a0.y, a0.z, a0.w, a1.x, a1.y, a1.z, a1.w};
            float rb[8] = {b0.x, b0.y, b0.z, b0.w, b1.x, b1.y, b1.z, b1.w};
            #pragma unroll
            for (int i = 0; i < 8; i++)
                #pragma unroll
                for (int j = 0; j < 8; j++) acc[i][j] += ra[i] * rb[j];
        }
        if (it + 1 < KSTEPS) {
            store_smem(1 - cur);   // safe: no live readers of buf 1-cur
            __syncthreads();
        }
    }

    #pragma unroll
    for (int i = 0; i < 8; i++) {
        int m = m0 + ((i < 4) ? (ty * 4 + i) : (64 + ty * 4 + (i - 4)));
        if (m >= M) continue;
        int nA = n0 + tx * 4;
        int nB = n0 + 64 + tx * 4;
        float4 vA = make_float4(acc[i][0], acc[i][1], acc[i][2], acc[i][3]);
        float4 vB = make_float4(acc[i][4], acc[i][5], acc[i][6], acc[i][7]);
        if (bias) {
            vA.x += bias[nA + 0]; vA.y += bias[nA + 1];
            vA.z += bias[nA + 2]; vA.w += bias[nA + 3];
            vB.x += bias[nB + 0]; vB.y += bias[nB + 1];
            vB.z += bias[nB + 2]; vB.w += bias[nB + 3];
        }
        *(float4*)&Cmat[(size_t)m * CH + nA] = vA;
        *(float4*)&Cmat[(size_t)m * CH + nB] = vB;
    }
}

// ---------------------------------------------------------------------------
// Fused QKV projection, exact flat grid (no dead CTAs): 891 CTAs.
// ---------------------------------------------------------------------------
#define QTILES 197
#define KVTILES 50
#define QKV_CTAS ((QTILES + 2 * KVTILES) * 3)

__global__ __launch_bounds__(256, 2) void qkv_gemm(
    const float* __restrict__ wq, const float* __restrict__ wk,
    const float* __restrict__ wv)
{
    __shared__ GemmSmem sm;
    int bid = blockIdx.x;
    int nt = bid % 3;
    int mt = bid / 3;
    const float* A; const float* W; float* C; int M; int m0;
    if (mt < QTILES) {
        A = g_qin; W = wq; C = g_q; M = MQ;  m0 = mt * GBM;
    } else if (mt < QTILES + KVTILES) {
        A = g_kin; W = wk; C = g_k; M = MKV; m0 = (mt - QTILES) * GBM;
    } else {
        A = g_vin; W = wv; C = g_v; M = MKV; m0 = (mt - QTILES - KVTILES) * GBM;
    }
    gemm_body(A, W, nullptr, C, M, m0, nt * GBN, sm);
}

__global__ __launch_bounds__(256, 2) void proj_gemm(
    const float* __restrict__ wproj, const float* __restrict__ bproj,
    float* __restrict__ out)
{
    __shared__ GemmSmem sm;
    gemm_body(g_att, wproj, bproj, out, MQ, blockIdx.y * GBM,
              blockIdx.x * GBN, sm);
}

// ---------------------------------------------------------------------------
// Fused attention: per (b, head, 64-query tile).
// KSTR=68 (multiple of 4): K/Q rows float4-aligned; LDS.128 phase analysis:
//   row base bank = 4*j mod 32, lanes of a phase start at 0,4,...,28 and
//   cover 4 consecutive banks each -> conflict-free.
// QK^T loop vectorized over d (float4): 11 LDS.128 + 112 FFMA per 4-d step.
// PV loop: P rows read as broadcast float4 per 4-j chunk.
// ---------------------------------------------------------------------------
#define QT 64
#define PSTR 200
#define KSTR 68

__global__ __launch_bounds__(512) void attn_kernel()
{
    extern __shared__ float smf[];
    float* ks = smf;                        // TKN * KSTR
    float* vs = ks + TKN * KSTR;            // TKN * KSTR
    float* qs = vs + TKN * KSTR;            // QT * KSTR
    float* ps = qs + QT * KSTR;             // QT * PSTR
    int b = blockIdx.z, h = blockIdx.y;
    int qt0 = blockIdx.x * QT;
    int tid = threadIdx.x;

    for (int i = tid; i < TKN * (HDIM / 4); i += 512) {
        int j = i / (HDIM / 4);
        int d4 = i % (HDIM / 4);
        float4 kv = *(const float4*)&g_k[(b * TKN + j) * CH + h * HDIM + d4 * 4];
        float4 vv = *(const float4*)&g_v[(b * TKN + j) * CH + h * HDIM + d4 * 4];
        *(float4*)&ks[j * KSTR + d4 * 4] = kv;
        *(float4*)&vs[j * KSTR + d4 * 4] = vv;
    }
    for (int i = tid; i < QT * (HDIM / 4); i += 512) {
        int qi = i / (HDIM / 4);
        int d4 = i % (HDIM / 4);
        int t = qt0 + qi;
        float4 qv = (t < TQN) ? *(const float4*)&g_q[(b * TQN + t) * CH + h * HDIM + d4 * 4]
                              : make_float4(0.f, 0.f, 0.f, 0.f);
        *(float4*)&qs[qi * KSTR + d4 * 4] = qv;
    }
    __syncthreads();

    int tx = tid & 31;
    int ty = tid >> 5;
    int q0 = ty * 4;

    // ---- scores: s[q][jj], j = tx + 32*jj, vectorized over d ----
    float s[4][7];
    #pragma unroll
    for (int q = 0; q < 4; q++)
        #pragma unroll
        for (int jj = 0; jj < 7; jj++) s[q][jj] = 0.f;

    #pragma unroll 4
    for (int d4 = 0; d4 < HDIM / 4; d4++) {
        float4 kv[7];
        #pragma unroll
        for (int jj = 0; jj < 7; jj++) {
            int j = tx + jj * 32;
            kv[jj] = (j < TKN) ? *(const float4*)&ks[j * KSTR + d4 * 4]
                               : make_float4(0.f, 0.f, 0.f, 0.f);
        }
        #pragma unroll
        for (int q = 0; q < 4; q++) {
            float4 qv = *(const float4*)&qs[(q0 + q) * KSTR + d4 * 4];
            #pragma unroll
            for (int jj = 0; jj < 7; jj++) {
                s[q][jj] += qv.x * kv[jj].x;
                s[q][jj] += qv.y * kv[jj].y;
                s[q][jj] += qv.z * kv[jj].z;
                s[q][jj] += qv.w * kv[jj].w;
            }
        }
    }

    // ---- softmax per query row, reduced across the warp ----
    #pragma unroll
    for (int q = 0; q < 4; q++) {
        float mx = -1e30f;
        #pragma unroll
        for (int jj = 0; jj < 7; jj++) {
            int j = tx + jj * 32;
            float sv = s[q][jj] * SCALE_F;
            s[q][jj] = sv;
            if (j < TKN) mx = fmaxf(mx, sv);
        }
        #pragma unroll
        for (int o = 16; o; o >>= 1)
            mx = fmaxf(mx, __shfl_xor_sync(0xffffffffu, mx, o));
        float sum = 0.f;
        #pragma unroll
        for (int jj = 0; jj < 7; jj++) {
            int j = tx + jj * 32;
            if (j < TKN) {
                float p = __expf(s[q][jj] - mx);
                s[q][jj] = p;
                sum += p;
            }
        }
        #pragma unroll
        for (int o = 16; o; o >>= 1)
            sum += __shfl_xor_sync(0xffffffffu, sum, o);
        float rinv = 1.f / sum;
        #pragma unroll
        for (int jj = 0; jj < 7; jj++) {
            int j = tx + jj * 32;
            if (j < TKN) ps[(q0 + q) * PSTR + j] = s[q][jj] * rinv;
        }
    }
    __syncwarp();   // ps rows for this warp's queries written only by this warp

    // ---- PV: out[q][d], d = tx and tx+32; P read as float4 per 4-j ----
    float acc[4][2];
    #pragma unroll
    for (int q = 0; q < 4; q++) { acc[q][0] = 0.f; acc[q][1] = 0.f; }

    for (int j0 = 0; j0 + 4 <= TKN; j0 += 4) {
        float4 pv[4];
        #pragma unroll
        for (int q = 0; q < 4; q++)
            pv[q] = *(const float4*)&ps[(q0 + q) * PSTR + j0];
        #pragma unroll
        for (int jj = 0; jj < 4; jj++) {
            float v0 = vs[(j0 + jj) * KSTR + tx];
            float v1 = vs[(j0 + jj) * KSTR + tx + 32];
            #pragma unroll
            for (int q = 0; q < 4; q++) {
                float p = (jj == 0) ? pv[q].x : (jj == 1) ? pv[q].y
                        : (jj == 2) ? pv[q].z : pv[q].w;
                acc[q][0] += p * v0;
                acc[q][1] += p * v1;
            }
        }
    }
    { // tail: j = 196
        int j = TKN - 1;
        float v0 = vs[j * KSTR + tx];
        float v1 = vs[j * KSTR + tx + 32];
        #pragma unroll
        for (int q = 0; q < 4; q++) {
            float p = ps[(q0 + q) * PSTR + j];
            acc[q][0] += p * v0;
            acc[q][1] += p * v1;
        }
    }

    #pragma unroll
    for (int q = 0; q < 4; q++) {
        int t = qt0 + q0 + q;
        if (t < TQN) {
            float* orow = &g_att[(b * TQN + t) * CH + h * HDIM];
            orow[tx]      = acc[q][0];
            orow[tx + 32] = acc[q][1];
        }
    }
}

// ---------------------------------------------------------------------------
// Launch
// ---------------------------------------------------------------------------
extern "C" void kernel_launch(void* const* d_in, const int* in_sizes, int n_in,
                              void* d_out, int out_size)
{
    const float* x      = (const float*)d_in[0];
    const float* conv_w = (const float*)d_in[1];
    const float* bng    = (const float*)d_in[2];
    const float* bnb    = (const float*)d_in[3];
    const float* bnm    = (const float*)d_in[4];
    const float* bnv    = (const float*)d_in[5];
    const float* w_q    = (const float*)d_in[6];
    const float* w_k    = (const float*)d_in[7];
    const float* w_v    = (const float*)d_in[8];
    const float* w_proj = (const float*)d_in[9];
    const float* b_proj = (const float*)d_in[10];
    float* out = (float*)d_out;

    // 1) conv + BN token embeddings (float4 over channels)
    int nq = BATCH * TQN * C4;
    convq_kernel<<<(nq + 255) / 256, 256>>>(x, conv_w, bng, bnb, bnm, bnv);
    int nkv = BATCH * TKN * C4;
    convkv_kernel<<<(nkv + 255) / 256, 256>>>(x, conv_w, bng, bnb, bnm, bnv);

    // 2) fused QKV projections (exact flat grid, 891 CTAs)
    qkv_gemm<<<QKV_CTAS, 256>>>(w_q, w_k, w_v);

    // 3) fused attention
    size_t smem = (size_t)(2 * TKN * KSTR + QT * KSTR + QT * PSTR) * sizeof(float);
    cudaFuncSetAttribute(attn_kernel, cudaFuncAttributeMaxDynamicSharedMemorySize,
                         (int)smem);
    attn_kernel<<<dim3((TQN + QT - 1) / QT, NHEADS, BATCH), 512, smem>>>();

    // 4) output projection (+bias) straight into d_out
    dim3 gproj(CH / GBN, (MQ + GBM - 1) / GBM);
    proj_gemm<<<gproj, 256>>>(w_proj, b_proj, out);
}